// round 1
// baseline (speedup 1.0000x reference)
#include <cuda_runtime.h>
#include <math.h>

#define DM   2048
#define NH   16
#define DH   128
#define TSEQ 2048
#define NB   2
#define ROWS (NB*TSEQ)   // 4096
#define BHN  (NB*NH)     // 32

// Scratch (device globals: allocation-free per harness rules)
__device__ float g_Q[(size_t)BHN*TSEQ*DH];   // (B,H,T,D)
__device__ float g_K[(size_t)BHN*TSEQ*DH];
__device__ float g_V[(size_t)BHN*TSEQ*DH];
__device__ float g_A[(size_t)ROWS*DM];       // attn out (B,T,H*D) row-major

// ---------------------------------------------------------------------------
// SGEMM: C[n][m] = sum_k A[n][k]*W[m][k] + bias[m]
// MODE 0: scatter into (B,H,T,D); MODE 1: plain row-major (ROWS x DM)
// Tiles: 128x128x16, 256 threads, 8x8 micro-tile.
// ---------------------------------------------------------------------------
template<int MODE>
__global__ __launch_bounds__(256) void sgemm_kernel(
    const float* __restrict__ A, const float* __restrict__ W,
    const float* __restrict__ bias, float* __restrict__ C)
{
    __shared__ float Xs[16][132];
    __shared__ float Ws[16][132];
    const int tid = threadIdx.x;
    const int tx = tid & 15, ty = tid >> 4;
    const int n0 = blockIdx.y * 128;
    const int m0 = blockIdx.x * 128;

    float acc[8][8];
#pragma unroll
    for (int i = 0; i < 8; i++)
#pragma unroll
        for (int j = 0; j < 8; j++) acc[i][j] = 0.f;

    for (int k0 = 0; k0 < DM; k0 += 16) {
#pragma unroll
        for (int l = 0; l < 2; l++) {
            int idx = tid + l * 256;      // 0..511
            int row = idx >> 2;           // 0..127
            int c4  = idx & 3;            // 0..3
            float4 va = *(const float4*)(A + (size_t)(n0 + row) * DM + k0 + c4 * 4);
            Xs[c4*4+0][row] = va.x; Xs[c4*4+1][row] = va.y;
            Xs[c4*4+2][row] = va.z; Xs[c4*4+3][row] = va.w;
            float4 vb = *(const float4*)(W + (size_t)(m0 + row) * DM + k0 + c4 * 4);
            Ws[c4*4+0][row] = vb.x; Ws[c4*4+1][row] = vb.y;
            Ws[c4*4+2][row] = vb.z; Ws[c4*4+3][row] = vb.w;
        }
        __syncthreads();
#pragma unroll
        for (int kk = 0; kk < 16; kk++) {
            float4 a0 = *(const float4*)&Xs[kk][ty*8];
            float4 a1 = *(const float4*)&Xs[kk][ty*8+4];
            float4 b0 = *(const float4*)&Ws[kk][tx*8];
            float4 b1 = *(const float4*)&Ws[kk][tx*8+4];
            float a[8] = {a0.x,a0.y,a0.z,a0.w,a1.x,a1.y,a1.z,a1.w};
            float b[8] = {b0.x,b0.y,b0.z,b0.w,b1.x,b1.y,b1.z,b1.w};
#pragma unroll
            for (int i = 0; i < 8; i++)
#pragma unroll
                for (int j = 0; j < 8; j++) acc[i][j] += a[i]*b[j];
        }
        __syncthreads();
    }

    const int m = m0 + tx*8;
    float bl[8];
#pragma unroll
    for (int j = 0; j < 8; j++) bl[j] = bias[m + j];
#pragma unroll
    for (int i = 0; i < 8; i++) {
        int n = n0 + ty*8 + i;
        float4 r0 = make_float4(acc[i][0]+bl[0], acc[i][1]+bl[1],
                                acc[i][2]+bl[2], acc[i][3]+bl[3]);
        float4 r1 = make_float4(acc[i][4]+bl[4], acc[i][5]+bl[5],
                                acc[i][6]+bl[6], acc[i][7]+bl[7]);
        float* dst;
        if (MODE == 1) {
            dst = C + (size_t)n * DM + m;
        } else {
            int b = n >> 11, t = n & (TSEQ-1);
            int h = m >> 7,  d = m & (DH-1);
            dst = C + (((size_t)(b*NH + h) * TSEQ + t) * DH + d);
        }
        *(float4*)dst     = r0;
        *(float4*)(dst+4) = r1;
    }
}

// ---------------------------------------------------------------------------
// RoPE: in-place on Q and K, (B,H,T,D) layout. grid (T, BH, 2), block 64.
// ---------------------------------------------------------------------------
__global__ void rope_kernel(float* __restrict__ Q, float* __restrict__ K,
                            const float* __restrict__ sinT,
                            const float* __restrict__ cosT)
{
    int t  = blockIdx.x;
    int bh = blockIdx.y;
    int d  = threadIdx.x;   // 0..63
    float* row = (blockIdx.z ? K : Q) + ((size_t)bh * TSEQ + t) * DH;
    float s = sinT[t*64 + d];
    float c = cosT[t*64 + d];
    float x1 = row[d], x2 = row[d+64];
    row[d]    = x1*c - x2*s;
    row[d+64] = x1*s + x2*c;
}

// ---------------------------------------------------------------------------
// Causal flash attention, fp32. BQ=BK=64, D=128, 256 threads.
// smem: Qs[64][128] Ks[64][132] Vs[64][128] Ps[64][65]  = 115968 B
// Thread (ty,tx) in 16x16: S micro-tile 4q x 4k, O micro-tile 4q x 8d.
// ---------------------------------------------------------------------------
#define SMEM_ATT ((64*128 + 64*132 + 64*128 + 64*65) * 4)

__global__ __launch_bounds__(256, 2) void attn_kernel()
{
    extern __shared__ float sm[];
    float* Qs = sm;                 // stride 128
    float* Ks = Qs + 64*128;        // stride 132
    float* Vs = Ks + 64*132;        // stride 128
    float* Ps = Vs + 64*128;        // stride 65

    const int tid = threadIdx.x;
    const int tx = tid & 15, ty = tid >> 4;
    const int qt = blockIdx.x;      // query tile
    const int bh = blockIdx.y;
    const int q0 = qt * 64;
    const float SCALE = 0.08838834764831845f;   // 1/sqrt(128)

    // Load Q tile (pre-scaled)
    const float* Qg = g_Q + ((size_t)bh * TSEQ + q0) * DH;
#pragma unroll
    for (int l = 0; l < 8; l++) {
        int idx = tid + l * 256;     // f4 id 0..2047
        int row = idx >> 5;          // 32 f4 per row
        int c   = idx & 31;
        float4 v = *(const float4*)(Qg + (size_t)row * DH + c * 4);
        v.x *= SCALE; v.y *= SCALE; v.z *= SCALE; v.w *= SCALE;
        *(float4*)&Qs[row*128 + c*4] = v;
    }

    float m_i[4], l_i[4], o[4][8];
#pragma unroll
    for (int i = 0; i < 4; i++) {
        m_i[i] = -1e30f; l_i[i] = 0.f;
#pragma unroll
        for (int j = 0; j < 8; j++) o[i][j] = 0.f;
    }

    for (int kt = 0; kt <= qt; kt++) {
        // Load K/V tiles
        const float* Kg = g_K + ((size_t)bh * TSEQ + kt*64) * DH;
        const float* Vg = g_V + ((size_t)bh * TSEQ + kt*64) * DH;
#pragma unroll
        for (int l = 0; l < 8; l++) {
            int idx = tid + l * 256;
            int row = idx >> 5;
            int c   = idx & 31;
            float4 vk = *(const float4*)(Kg + (size_t)row * DH + c * 4);
            *(float4*)&Ks[row*132 + c*4] = vk;
            float4 vv = *(const float4*)(Vg + (size_t)row * DH + c * 4);
            *(float4*)&Vs[row*128 + c*4] = vv;
        }
        __syncthreads();

        // S = Q * K^T  (4x4 micro-tile per thread)
        float s[4][4];
#pragma unroll
        for (int i = 0; i < 4; i++)
#pragma unroll
            for (int j = 0; j < 4; j++) s[i][j] = 0.f;

        const float4* Q4 = (const float4*)Qs;  // row stride 32 f4
        const float4* K4 = (const float4*)Ks;  // row stride 33 f4
#pragma unroll 8
        for (int kk = 0; kk < 32; kk++) {
            float4 a[4], b[4];
#pragma unroll
            for (int i = 0; i < 4; i++) a[i] = Q4[(ty*4+i)*32 + kk];
#pragma unroll
            for (int j = 0; j < 4; j++) b[j] = K4[(tx*4+j)*33 + kk];
#pragma unroll
            for (int i = 0; i < 4; i++)
#pragma unroll
                for (int j = 0; j < 4; j++) {
                    s[i][j] += a[i].x*b[j].x;
                    s[i][j] += a[i].y*b[j].y;
                    s[i][j] += a[i].z*b[j].z;
                    s[i][j] += a[i].w*b[j].w;
                }
        }

        if (kt == qt) {   // causal mask on diagonal tile
#pragma unroll
            for (int i = 0; i < 4; i++)
#pragma unroll
                for (int j = 0; j < 4; j++)
                    if (tx*4+j > ty*4+i) s[i][j] = -1e30f;
        }

        // online softmax
#pragma unroll
        for (int i = 0; i < 4; i++) {
            float mloc = s[i][0];
            mloc = fmaxf(mloc, s[i][1]);
            mloc = fmaxf(mloc, s[i][2]);
            mloc = fmaxf(mloc, s[i][3]);
#pragma unroll
            for (int off = 8; off; off >>= 1)
                mloc = fmaxf(mloc, __shfl_xor_sync(0xffffffffu, mloc, off));
            float mnew = fmaxf(m_i[i], mloc);
            float alpha = __expf(m_i[i] - mnew);
            float lsum = 0.f;
#pragma unroll
            for (int j = 0; j < 4; j++) {
                float p = __expf(s[i][j] - mnew);
                s[i][j] = p;
                lsum += p;
            }
#pragma unroll
            for (int off = 8; off; off >>= 1)
                lsum += __shfl_xor_sync(0xffffffffu, lsum, off);
            l_i[i] = l_i[i] * alpha + lsum;
            m_i[i] = mnew;
#pragma unroll
            for (int j = 0; j < 8; j++) o[i][j] *= alpha;
#pragma unroll
            for (int j = 0; j < 4; j++)
                Ps[(ty*4+i)*65 + tx*4 + j] = s[i][j];
        }
        __syncthreads();

        // O += P * V
        const float4* V4 = (const float4*)Vs;  // row stride 32 f4
#pragma unroll 8
        for (int kk = 0; kk < 64; kk++) {
            float4 v0 = V4[kk*32 + tx*2];
            float4 v1 = V4[kk*32 + tx*2 + 1];
#pragma unroll
            for (int i = 0; i < 4; i++) {
                float p = Ps[(ty*4+i)*65 + kk];
                o[i][0] += p * v0.x; o[i][1] += p * v0.y;
                o[i][2] += p * v0.z; o[i][3] += p * v0.w;
                o[i][4] += p * v1.x; o[i][5] += p * v1.y;
                o[i][6] += p * v1.z; o[i][7] += p * v1.w;
            }
        }
        __syncthreads();
    }

    // epilogue -> g_A in (B,T,H*D) row-major
    const int b = bh >> 4, h = bh & 15;
#pragma unroll
    for (int i = 0; i < 4; i++) {
        float inv = 1.0f / l_i[i];
        int q = q0 + ty*4 + i;
        float* dst = g_A + ((size_t)(b*TSEQ + q) * NH + h) * DH + tx*8;
        float4 r0 = make_float4(o[i][0]*inv, o[i][1]*inv, o[i][2]*inv, o[i][3]*inv);
        float4 r1 = make_float4(o[i][4]*inv, o[i][5]*inv, o[i][6]*inv, o[i][7]*inv);
        *(float4*)dst     = r0;
        *(float4*)(dst+4) = r1;
    }
}

// ---------------------------------------------------------------------------
extern "C" void kernel_launch(void* const* d_in, const int* in_sizes, int n_in,
                              void* d_out, int out_size)
{
    const float* x    = (const float*)d_in[0];
    const float* Wq   = (const float*)d_in[1];
    const float* bq   = (const float*)d_in[2];
    const float* Wk   = (const float*)d_in[3];
    const float* bk   = (const float*)d_in[4];
    const float* Wv   = (const float*)d_in[5];
    const float* bv   = (const float*)d_in[6];
    const float* Wo   = (const float*)d_in[7];
    const float* bo   = (const float*)d_in[8];
    const float* sinT = (const float*)d_in[9];
    const float* cosT = (const float*)d_in[10];
    float* out = (float*)d_out;

    float *Qp, *Kp, *Vp, *Ap;
    cudaGetSymbolAddress((void**)&Qp, g_Q);
    cudaGetSymbolAddress((void**)&Kp, g_K);
    cudaGetSymbolAddress((void**)&Vp, g_V);
    cudaGetSymbolAddress((void**)&Ap, g_A);

    cudaFuncSetAttribute(attn_kernel,
                         cudaFuncAttributeMaxDynamicSharedMemorySize, SMEM_ATT);

    dim3 gemm_grid(DM/128, ROWS/128);   // (16, 32)
    sgemm_kernel<0><<<gemm_grid, 256>>>(x, Wq, bq, Qp);
    sgemm_kernel<0><<<gemm_grid, 256>>>(x, Wk, bk, Kp);
    sgemm_kernel<0><<<gemm_grid, 256>>>(x, Wv, bv, Vp);

    rope_kernel<<<dim3(TSEQ, BHN, 2), 64>>>(Qp, Kp, sinT, cosT);

    attn_kernel<<<dim3(TSEQ/64, BHN), 256, SMEM_ATT>>>();

    sgemm_kernel<1><<<gemm_grid, 256>>>(Ap, Wo, bo, out);
}

// round 4
// speedup vs baseline: 1.0744x; 1.0744x over previous
#include <cuda_runtime.h>
#include <cstdint>
#include <math.h>

#define DM   2048
#define NH   16
#define DH   128
#define TSEQ 2048
#define NB   2
#define ROWS (NB*TSEQ)   // 4096
#define BHN  (NB*NH)     // 32

// Scratch (device globals: allocation-free per harness rules)
__device__ float g_Q[(size_t)BHN*TSEQ*DH];   // (B,H,T,D)
__device__ float g_K[(size_t)BHN*TSEQ*DH];
__device__ float g_V[(size_t)BHN*TSEQ*DH];
__device__ float g_A[(size_t)ROWS*DM];       // attn out (B,T,H*D) row-major

// ===========================================================================
// 3xTF32 tensor-core GEMM:  C[r][c] = sum_k A[r][k]*W[c][k] + bias[c]
// Block 128x128, k-step 32, 8 warps (warp tile 32x64), mma.m16n8k8.tf32.
// Global->smem via cp.async.cg 16B, 3-stage wait_group pipeline.
// MODE 0: scatter into (B,H,T,D); MODE 1: row-major (ROWS x DM).
// ===========================================================================
#define GBK      32
#define GSTAGES  3
#define TILE_F   36                     // padded floats per smem row (144B)
#define STAGE_F  (2*128*TILE_F)         // A tile then B tile
#define GEMM_SMEM (GSTAGES*STAGE_F*4)   // 110,592 B

__device__ __forceinline__ uint32_t cvta_s(const void* p) {
    return (uint32_t)__cvta_generic_to_shared(p);
}

__device__ __forceinline__ void cpasync16(void* dst, const void* src) {
    asm volatile("cp.async.cg.shared.global [%0], [%1], 16;\n"
                 :: "r"(cvta_s(dst)), "l"(src) : "memory");
}
#define CP_COMMIT() asm volatile("cp.async.commit_group;\n" ::: "memory")
#define CP_WAIT(n)  asm volatile("cp.async.wait_group %0;\n" :: "n"(n) : "memory")

#define MMA_TF32(c, a, b) \
    asm volatile("mma.sync.aligned.m16n8k8.row.col.f32.tf32.tf32.f32 " \
        "{%0,%1,%2,%3},{%4,%5,%6,%7},{%8,%9},{%0,%1,%2,%3};\n" \
        : "+f"((c)[0]), "+f"((c)[1]), "+f"((c)[2]), "+f"((c)[3]) \
        : "r"((a)[0]), "r"((a)[1]), "r"((a)[2]), "r"((a)[3]), \
          "r"((b)[0]), "r"((b)[1]))

template<int MODE>
__global__ __launch_bounds__(256, 1) void gemm_tf32(
    const float* __restrict__ A, const float* __restrict__ W,
    const float* __restrict__ bias, float* __restrict__ C)
{
    extern __shared__ float smem[];

    const int tid  = threadIdx.x;
    const int lane = tid & 31;
    const int warp = tid >> 5;
    const int gid  = lane >> 2;     // 0..7
    const int tg   = lane & 3;      // 0..3
    const int warpM = warp & 3;     // 0..3  (M: 4 x 32)
    const int warpN = warp >> 2;    // 0..1  (N: 2 x 64)
    const long r0b = (long)blockIdx.y * 128;   // token rows
    const long c0b = (long)blockIdx.x * 128;   // feature cols

    // Each thread owns one smem row (A rows for tid<128, W rows for tid>=128)
    const int row128 = tid & 127;
    const float* gsrc = (tid < 128)
        ? (A + (r0b + row128) * DM)
        : (W + (c0b + row128) * DM);
    float* sdst_base = smem + (tid < 128 ? 0 : 128*TILE_F) + row128 * TILE_F;

    // prologue: fill all stages
#pragma unroll
    for (int s = 0; s < GSTAGES; s++) {
#pragma unroll
        for (int c4 = 0; c4 < 8; c4++)
            cpasync16(sdst_base + s*STAGE_F + c4*4, gsrc + s*GBK + c4*4);
        CP_COMMIT();
    }

    float acc[2][8][4];
#pragma unroll
    for (int i = 0; i < 2; i++)
#pragma unroll
        for (int j = 0; j < 8; j++)
#pragma unroll
            for (int q = 0; q < 4; q++) acc[i][j][q] = 0.f;

    const int KITERS = DM / GBK;   // 64
    for (int kt = 0; kt < KITERS; kt++) {
        const int s = kt % GSTAGES;
        CP_WAIT(GSTAGES - 1);
        __syncthreads();

        const float* As = smem + s*STAGE_F;
        const float* Bs = As + 128*TILE_F;

#pragma unroll
        for (int ks = 0; ks < 4; ks++) {
            const int kc = ks*8 + tg;

            uint32_t ahi[2][4], alo[2][4];
#pragma unroll
            for (int i = 0; i < 2; i++) {
                const int r = warpM*32 + i*16 + gid;
#pragma unroll
                for (int q = 0; q < 4; q++) {
                    const int rr = r + (q & 1) * 8;
                    const int cc = kc + (q >> 1) * 4;
                    float x = As[rr*TILE_F + cc];
                    uint32_t h = __float_as_uint(x) & 0xFFFFE000u;
                    ahi[i][q] = h;
                    alo[i][q] = __float_as_uint(x - __uint_as_float(h));
                }
            }
            uint32_t bhi[8][2], blo[8][2];
#pragma unroll
            for (int j = 0; j < 8; j++) {
                const int n = warpN*64 + j*8 + gid;
#pragma unroll
                for (int q = 0; q < 2; q++) {
                    float x = Bs[n*TILE_F + kc + q*4];
                    uint32_t h = __float_as_uint(x) & 0xFFFFE000u;
                    bhi[j][q] = h;
                    blo[j][q] = __float_as_uint(x - __uint_as_float(h));
                }
            }
#pragma unroll
            for (int i = 0; i < 2; i++)
#pragma unroll
                for (int j = 0; j < 8; j++) {
                    MMA_TF32(acc[i][j], ahi[i], bhi[j]);
                    MMA_TF32(acc[i][j], ahi[i], blo[j]);
                    MMA_TF32(acc[i][j], alo[i], bhi[j]);
                }
        }
        __syncthreads();
        const int nk = kt + GSTAGES;
        if (nk < KITERS) {
#pragma unroll
            for (int c4 = 0; c4 < 8; c4++)
                cpasync16(sdst_base + s*STAGE_F + c4*4, gsrc + nk*GBK + c4*4);
        }
        CP_COMMIT();   // commit every iter (possibly empty) to keep group count in sync
    }

    // epilogue
#pragma unroll
    for (int i = 0; i < 2; i++) {
        const long r0 = r0b + warpM*32 + i*16 + gid;
        const long r1 = r0 + 8;
#pragma unroll
        for (int j = 0; j < 8; j++) {
            const long col = c0b + warpN*64 + j*8 + 2*tg;
            float2 bl = *(const float2*)(bias + col);
            float2 v0 = make_float2(acc[i][j][0] + bl.x, acc[i][j][1] + bl.y);
            float2 v1 = make_float2(acc[i][j][2] + bl.x, acc[i][j][3] + bl.y);
            if (MODE == 1) {
                *(float2*)(C + r0*DM + col) = v0;
                *(float2*)(C + r1*DM + col) = v1;
            } else {
                const long h = col >> 7, d = col & 127;
                *(float2*)(C + (((r0 >> 11)*NH + h)*TSEQ + (r0 & 2047))*DH + d) = v0;
                *(float2*)(C + (((r1 >> 11)*NH + h)*TSEQ + (r1 & 2047))*DH + d) = v1;
            }
        }
    }
}

// ---------------------------------------------------------------------------
// RoPE: in-place on Q and K, (B,H,T,D) layout. grid (T/4, BH, 2), block 256.
// ---------------------------------------------------------------------------
__global__ void rope_kernel(float* __restrict__ Q, float* __restrict__ K,
                            const float* __restrict__ sinT,
                            const float* __restrict__ cosT)
{
    int t  = blockIdx.x * 4 + (threadIdx.x >> 6);
    int bh = blockIdx.y;
    int d  = threadIdx.x & 63;
    float* row = (blockIdx.z ? K : Q) + ((size_t)bh * TSEQ + t) * DH;
    float s = sinT[t*64 + d];
    float c = cosT[t*64 + d];
    float x1 = row[d], x2 = row[d+64];
    row[d]    = x1*c - x2*s;
    row[d+64] = x1*s + x2*c;
}

// ---------------------------------------------------------------------------
// Causal flash attention, fp32 SIMT. BQ=BK=64, D=128, 256 threads.
// ---------------------------------------------------------------------------
#define SMEM_ATT ((64*128 + 64*132 + 64*128 + 64*65) * 4)

__global__ __launch_bounds__(256, 2) void attn_kernel()
{
    extern __shared__ float sm[];
    float* Qs = sm;                 // stride 128
    float* Ks = Qs + 64*128;        // stride 132
    float* Vs = Ks + 64*132;        // stride 128
    float* Ps = Vs + 64*128;        // stride 65

    const int tid = threadIdx.x;
    const int tx = tid & 15, ty = tid >> 4;
    const int qt = blockIdx.x;
    const int bh = blockIdx.y;
    const int q0 = qt * 64;
    const float SCALE = 0.08838834764831845f;   // 1/sqrt(128)

    const float* Qg = g_Q + ((size_t)bh * TSEQ + q0) * DH;
#pragma unroll
    for (int l = 0; l < 8; l++) {
        int idx = tid + l * 256;
        int row = idx >> 5;
        int c   = idx & 31;
        float4 v = *(const float4*)(Qg + (size_t)row * DH + c * 4);
        v.x *= SCALE; v.y *= SCALE; v.z *= SCALE; v.w *= SCALE;
        *(float4*)&Qs[row*128 + c*4] = v;
    }

    float m_i[4], l_i[4], o[4][8];
#pragma unroll
    for (int i = 0; i < 4; i++) {
        m_i[i] = -1e30f; l_i[i] = 0.f;
#pragma unroll
        for (int j = 0; j < 8; j++) o[i][j] = 0.f;
    }

    for (int kt = 0; kt <= qt; kt++) {
        const float* Kg = g_K + ((size_t)bh * TSEQ + kt*64) * DH;
        const float* Vg = g_V + ((size_t)bh * TSEQ + kt*64) * DH;
#pragma unroll
        for (int l = 0; l < 8; l++) {
            int idx = tid + l * 256;
            int row = idx >> 5;
            int c   = idx & 31;
            float4 vk = *(const float4*)(Kg + (size_t)row * DH + c * 4);
            *(float4*)&Ks[row*132 + c*4] = vk;
            float4 vv = *(const float4*)(Vg + (size_t)row * DH + c * 4);
            *(float4*)&Vs[row*128 + c*4] = vv;
        }
        __syncthreads();

        float s[4][4];
#pragma unroll
        for (int i = 0; i < 4; i++)
#pragma unroll
            for (int j = 0; j < 4; j++) s[i][j] = 0.f;

        const float4* Q4 = (const float4*)Qs;  // row stride 32 f4
        const float4* K4 = (const float4*)Ks;  // row stride 33 f4
#pragma unroll 8
        for (int kk = 0; kk < 32; kk++) {
            float4 a[4], b[4];
#pragma unroll
            for (int i = 0; i < 4; i++) a[i] = Q4[(ty*4+i)*32 + kk];
#pragma unroll
            for (int j = 0; j < 4; j++) b[j] = K4[(tx*4+j)*33 + kk];
#pragma unroll
            for (int i = 0; i < 4; i++)
#pragma unroll
                for (int j = 0; j < 4; j++) {
                    s[i][j] += a[i].x*b[j].x;
                    s[i][j] += a[i].y*b[j].y;
                    s[i][j] += a[i].z*b[j].z;
                    s[i][j] += a[i].w*b[j].w;
                }
        }

        if (kt == qt) {
#pragma unroll
            for (int i = 0; i < 4; i++)
#pragma unroll
                for (int j = 0; j < 4; j++)
                    if (tx*4+j > ty*4+i) s[i][j] = -1e30f;
        }

#pragma unroll
        for (int i = 0; i < 4; i++) {
            float mloc = s[i][0];
            mloc = fmaxf(mloc, s[i][1]);
            mloc = fmaxf(mloc, s[i][2]);
            mloc = fmaxf(mloc, s[i][3]);
#pragma unroll
            for (int off = 8; off; off >>= 1)
                mloc = fmaxf(mloc, __shfl_xor_sync(0xffffffffu, mloc, off));
            float mnew = fmaxf(m_i[i], mloc);
            float alpha = __expf(m_i[i] - mnew);
            float lsum = 0.f;
#pragma unroll
            for (int j = 0; j < 4; j++) {
                float p = __expf(s[i][j] - mnew);
                s[i][j] = p;
                lsum += p;
            }
#pragma unroll
            for (int off = 8; off; off >>= 1)
                lsum += __shfl_xor_sync(0xffffffffu, lsum, off);
            l_i[i] = l_i[i] * alpha + lsum;
            m_i[i] = mnew;
#pragma unroll
            for (int j = 0; j < 8; j++) o[i][j] *= alpha;
#pragma unroll
            for (int j = 0; j < 4; j++)
                Ps[(ty*4+i)*65 + tx*4 + j] = s[i][j];
        }
        __syncthreads();

        const float4* V4 = (const float4*)Vs;  // row stride 32 f4
#pragma unroll 8
        for (int kk = 0; kk < 64; kk++) {
            float4 v0 = V4[kk*32 + tx*2];
            float4 v1 = V4[kk*32 + tx*2 + 1];
#pragma unroll
            for (int i = 0; i < 4; i++) {
                float p = Ps[(ty*4+i)*65 + kk];
                o[i][0] += p * v0.x; o[i][1] += p * v0.y;
                o[i][2] += p * v0.z; o[i][3] += p * v0.w;
                o[i][4] += p * v1.x; o[i][5] += p * v1.y;
                o[i][6] += p * v1.z; o[i][7] += p * v1.w;
            }
        }
        __syncthreads();
    }

    const int b = bh >> 4, h = bh & 15;
#pragma unroll
    for (int i = 0; i < 4; i++) {
        float inv = 1.0f / l_i[i];
        int q = q0 + ty*4 + i;
        float* dst = g_A + ((size_t)(b*TSEQ + q) * NH + h) * DH + tx*8;
        float4 r0 = make_float4(o[i][0]*inv, o[i][1]*inv, o[i][2]*inv, o[i][3]*inv);
        float4 r1 = make_float4(o[i][4]*inv, o[i][5]*inv, o[i][6]*inv, o[i][7]*inv);
        *(float4*)dst     = r0;
        *(float4*)(dst+4) = r1;
    }
}

// ---------------------------------------------------------------------------
extern "C" void kernel_launch(void* const* d_in, const int* in_sizes, int n_in,
                              void* d_out, int out_size)
{
    const float* x    = (const float*)d_in[0];
    const float* Wq   = (const float*)d_in[1];
    const float* bq   = (const float*)d_in[2];
    const float* Wk   = (const float*)d_in[3];
    const float* bk   = (const float*)d_in[4];
    const float* Wv   = (const float*)d_in[5];
    const float* bv   = (const float*)d_in[6];
    const float* Wo   = (const float*)d_in[7];
    const float* bo   = (const float*)d_in[8];
    const float* sinT = (const float*)d_in[9];
    const float* cosT = (const float*)d_in[10];
    float* out = (float*)d_out;

    float *Qp, *Kp, *Vp, *Ap;
    cudaGetSymbolAddress((void**)&Qp, g_Q);
    cudaGetSymbolAddress((void**)&Kp, g_K);
    cudaGetSymbolAddress((void**)&Vp, g_V);
    cudaGetSymbolAddress((void**)&Ap, g_A);

    cudaFuncSetAttribute(gemm_tf32<0>,
                         cudaFuncAttributeMaxDynamicSharedMemorySize, GEMM_SMEM);
    cudaFuncSetAttribute(gemm_tf32<1>,
                         cudaFuncAttributeMaxDynamicSharedMemorySize, GEMM_SMEM);
    cudaFuncSetAttribute(attn_kernel,
                         cudaFuncAttributeMaxDynamicSharedMemorySize, SMEM_ATT);

    dim3 gemm_grid(DM/128, ROWS/128);   // (16, 32)
    gemm_tf32<0><<<gemm_grid, 256, GEMM_SMEM>>>(x, Wq, bq, Qp);
    gemm_tf32<0><<<gemm_grid, 256, GEMM_SMEM>>>(x, Wk, bk, Kp);
    gemm_tf32<0><<<gemm_grid, 256, GEMM_SMEM>>>(x, Wv, bv, Vp);

    rope_kernel<<<dim3(TSEQ/4, BHN, 2), 256>>>(Qp, Kp, sinT, cosT);

    attn_kernel<<<dim3(TSEQ/64, BHN), 256, SMEM_ATT>>>();

    gemm_tf32<1><<<gemm_grid, 256, GEMM_SMEM>>>(Ap, Wo, bo, out);
}